// round 6
// baseline (speedup 1.0000x reference)
#include <cuda_runtime.h>

// Trilinear resize [4,128,128,128,2] f32 -> [4,192,192,192,2] f32, zoom=1.5.
// Exact 3-out-per-2-in periodicity, weights {1, 1/3, 2/3}.
// Block = (b, zkq, yk): z-QUAD of micro-blocks. Input tile [9z][3y][128x]
// staged in smem (coalesced batch load, latency hidden); output 192x3x12
// produced by streaming over 4 z micro-blocks, carrying the shared boundary
// plane in registers. 36 perfectly coalesced STG.64 per thread.

#define IN_D  128
#define OUT_D 192

__device__ __forceinline__ float2 lerp2(float2 a, float2 b, float wa, float wb) {
    return make_float2(fmaf(a.x, wa, b.x * wb), fmaf(a.y, wa, b.y * wb));
}

__global__ __launch_bounds__(192) void resize_zquad_kernel(
    const float2* __restrict__ in,   // [4,128,128,128] voxels (C=2 packed)
    float2* __restrict__ out)        // [4,192,192,192] voxels
{
    __shared__ float2 tile[27][IN_D];   // [zi*3+yi][x], 27648 B

    const int blk = blockIdx.x;
    const int yk  = blk & 63;
    const int zkq = (blk >> 6) & 15;
    const int b   = blk >> 10;

    const int t = threadIdx.x;          // 0..191

    const float2* base = in + (size_t)b * (IN_D * IN_D * IN_D);

    // ---- Phase 1: cooperative coalesced load of 27 input rows ----
    #pragma unroll
    for (int i = 0; i < 18; i++) {
        int idx = i * 192 + t;          // 0..3455
        int x = idx & 127;
        int r = idx >> 7;               // 0..26
        int zi = r / 3;
        int yi = r - 3 * zi;
        int z = min(8 * zkq + zi, IN_D - 1);
        int y = min(2 * yk + yi, IN_D - 1);
        tile[r][x] = __ldg(base + ((size_t)z * IN_D + y) * IN_D + x);
    }
    __syncthreads();

    const float c13 = 1.0f / 3.0f;
    const float c23 = 2.0f / 3.0f;

    // x-taps and weights for this output column (m = t % 3)
    const int q = t / 3;
    const int m = t - 3 * q;
    int xA, xB;
    float wA;
    if (m == 0)      { xA = 2 * q;     xB = xA;                       wA = 1.0f; }
    else if (m == 1) { xA = 2 * q;     xB = 2 * q + 1;                wA = c13;  }
    else             { xA = 2 * q + 1; xB = min(2 * q + 2, IN_D - 1); wA = c23;  }
    const float wB = 1.0f - wA;

    // compute x-lerped + y-lerped values for input plane zi
    auto plane_yl = [&](int zi, float2 yl[3]) {
        float2 xv[3];
        #pragma unroll
        for (int yi = 0; yi < 3; yi++) {
            float2 a = tile[zi * 3 + yi][xA];
            float2 c = tile[zi * 3 + yi][xB];
            xv[yi] = lerp2(a, c, wA, wB);
        }
        yl[0] = xv[0];
        yl[1] = lerp2(xv[0], xv[1], c13, c23);
        yl[2] = lerp2(xv[1], xv[2], c23, c13);
    };

    float2 yl0[3], yl1[3], yl2[3];
    plane_yl(0, yl0);

    size_t obase = (((size_t)b * OUT_D + 12 * zkq) * OUT_D + 3 * yk) * OUT_D + t;

    #pragma unroll
    for (int g = 0; g < 4; g++) {
        plane_yl(2 * g + 1, yl1);
        plane_yl(2 * g + 2, yl2);

        size_t zb = obase + (size_t)(3 * g) * (OUT_D * OUT_D);
        #pragma unroll
        for (int yo = 0; yo < 3; yo++) {
            out[zb + (size_t)(0 * OUT_D + yo) * OUT_D] = yl0[yo];
            out[zb + (size_t)(1 * OUT_D + yo) * OUT_D] =
                lerp2(yl0[yo], yl1[yo], c13, c23);
            out[zb + (size_t)(2 * OUT_D + yo) * OUT_D] =
                lerp2(yl1[yo], yl2[yo], c23, c13);
        }

        yl0[0] = yl2[0];
        yl0[1] = yl2[1];
        yl0[2] = yl2[2];
    }
}

extern "C" void kernel_launch(void* const* d_in, const int* in_sizes, int n_in,
                              void* d_out, int out_size) {
    const float2* in = (const float2*)d_in[0];
    float2* out = (float2*)d_out;

    int blocks = 4 * 16 * 64;   // (b, zkq, yk) = 4096
    resize_zquad_kernel<<<blocks, 192>>>(in, out);
}

// round 7
// speedup vs baseline: 1.0875x; 1.0875x over previous
#include <cuda_runtime.h>

// Trilinear resize [4,128,128,128,2] f32 -> [4,192,192,192,2] f32, zoom=1.5.
// Exact 3-out-per-2-in periodicity, weights {1, 1/3, 2/3}.
// R3 skeleton + y-pair blocks (384 thr) + float4 cooperative loads.
// Block = (b, zk, ykp): input tile [3z][5y][128x] in smem, output 192x6x3.
// Thread = one output x column for one of the two y micro-blocks:
// 18 LDS + 27 perfectly coalesced STG.64, regs ~32.

#define IN_D  128
#define OUT_D 192

__device__ __forceinline__ float2 lerp2(float2 a, float2 b, float wa, float wb) {
    return make_float2(fmaf(a.x, wa, b.x * wb), fmaf(a.y, wa, b.y * wb));
}

__global__ __launch_bounds__(384) void resize_ypair_kernel(
    const float2* __restrict__ in,   // [4,128,128,128] voxels (C=2 packed)
    float2* __restrict__ out)        // [4,192,192,192] voxels
{
    __shared__ float2 tile[15][IN_D];   // [zi*5+yj][x], 15360 B

    const int blk = blockIdx.x;
    const int ykp = blk & 31;           // y pair-block 0..31
    const int zk  = (blk >> 5) & 63;    // z micro-block 0..63
    const int b   = blk >> 11;

    const int t = threadIdx.x;          // 0..383

    const float4* in4 = (const float4*)(in + (size_t)b * (IN_D * IN_D * IN_D));
    float4* tile4 = (float4*)tile;

    // ---- Phase 1: cooperative float4 load of 15 input rows (960 float4) ----
    #pragma unroll
    for (int i = 0; i < 3; i++) {
        int idx = i * 384 + t;          // 0..959 (last iter: t<192 only)
        if (i < 2 || t < 192) {
            int f4 = idx & 63;          // float4 index within row (x = 2*f4)
            int r  = idx >> 6;          // 0..14
            int zi = r / 5;
            int yj = r - 5 * zi;
            int z = min(2 * zk + zi, IN_D - 1);
            int y = min(4 * ykp + yj, IN_D - 1);
            tile4[idx] = __ldg(in4 + ((size_t)z * IN_D + y) * 64 + f4);
        }
    }
    __syncthreads();

    const float c13 = 1.0f / 3.0f;
    const float c23 = 2.0f / 3.0f;

    const int xcol = t % 192;           // output x column
    const int yg   = t / 192;           // which y micro-block of the pair

    // x-taps and weights for this output column (m = xcol % 3)
    const int q = xcol / 3;
    const int m = xcol - 3 * q;
    int xA, xB;
    float wA;
    if (m == 0)      { xA = 2 * q;     xB = xA;                       wA = 1.0f; }
    else if (m == 1) { xA = 2 * q;     xB = 2 * q + 1;                wA = c13;  }
    else             { xA = 2 * q + 1; xB = min(2 * q + 2, IN_D - 1); wA = c23;  }
    const float wB = 1.0f - wA;

    // x-lerp from smem + y-lerp, per input z plane
    float2 yl[3][3];                    // [zi][yo]
    #pragma unroll
    for (int zi = 0; zi < 3; zi++) {
        float2 xv[3];
        #pragma unroll
        for (int yi = 0; yi < 3; yi++) {
            int r = zi * 5 + 2 * yg + yi;
            float2 a = tile[r][xA];
            float2 c = tile[r][xB];
            xv[yi] = lerp2(a, c, wA, wB);
        }
        yl[zi][0] = xv[0];
        yl[zi][1] = lerp2(xv[0], xv[1], c13, c23);
        yl[zi][2] = lerp2(xv[1], xv[2], c23, c13);
    }

    // z-lerp + 27 coalesced stores (thread writes column xcol of each row)
    size_t obase = (((size_t)b * OUT_D + 3 * zk) * OUT_D + (6 * ykp + 3 * yg))
                       * OUT_D + xcol;
    #pragma unroll
    for (int yo = 0; yo < 3; yo++) {
        float2 v0 = yl[0][yo];
        float2 v1 = yl[1][yo];
        float2 v2 = yl[2][yo];
        out[obase + (size_t)(0 * OUT_D + yo) * OUT_D] = v0;
        out[obase + (size_t)(1 * OUT_D + yo) * OUT_D] = lerp2(v0, v1, c13, c23);
        out[obase + (size_t)(2 * OUT_D + yo) * OUT_D] = lerp2(v1, v2, c23, c13);
    }
}

extern "C" void kernel_launch(void* const* d_in, const int* in_sizes, int n_in,
                              void* d_out, int out_size) {
    const float2* in = (const float2*)d_in[0];
    float2* out = (float2*)d_out;

    int blocks = 4 * 64 * 32;   // (b, zk, ykp) = 8192
    resize_ypair_kernel<<<blocks, 384>>>(in, out);
}